// round 3
// baseline (speedup 1.0000x reference)
#include <cuda_runtime.h>

// UpsampleLayer2D: x[B,R,C,64] -> out[B,2R,2C,16]
// out[b, ro, co, c] = x[b, ro%R, co%C, 4c + q],  q = 2*(ro>=R) + (co>=C)
//
// R3: 256-bit loads/stores (sm_100+ ld/st.global.v8.f32).
// 2 threads per input pixel: thread t loads channels [32t,32t+32) as 4x 32B
// (warp = 4KB contiguous read), per quadrant stores out channels [8t,8t+8)
// as one 32B store (warp = 1KB contiguous per quadrant stream).

#define B_  32
#define R_  200
#define C_  200
#define NPIX (B_ * R_ * C_)        // 1,280,000
#define NTH  (NPIX * 2)            // 2,560,000 threads

#define LDG256(p, o) \
    asm("ld.global.v8.f32 {%0,%1,%2,%3,%4,%5,%6,%7}, [%8];" \
        : "=f"(v[(o)+0]), "=f"(v[(o)+1]), "=f"(v[(o)+2]), "=f"(v[(o)+3]), \
          "=f"(v[(o)+4]), "=f"(v[(o)+5]), "=f"(v[(o)+6]), "=f"(v[(o)+7]) \
        : "l"((p) + (o)))

#define STG256(p, q) \
    asm volatile("st.global.v8.f32 [%0], {%1,%2,%3,%4,%5,%6,%7,%8};" \
        :: "l"(p), \
           "f"(v[0+(q)]),  "f"(v[4+(q)]),  "f"(v[8+(q)]),  "f"(v[12+(q)]), \
           "f"(v[16+(q)]), "f"(v[20+(q)]), "f"(v[24+(q)]), "f"(v[28+(q)]) \
        : "memory")

__global__ __launch_bounds__(256)
void upsample_kernel(const float* __restrict__ in, float* __restrict__ out) {
    const int idx = blockIdx.x * blockDim.x + threadIdx.x;
    if (idx >= NTH) return;

    const int t   = idx & 1;       // half-channel role: channels [32t, 32t+32)
    const int pix = idx >> 1;

    const int col = pix % C_;
    const int tmp = pix / C_;
    const int row = tmp % R_;
    const int b   = tmp / R_;

    // 32 contiguous input floats (128B), 4x 256-bit loads, front-batched.
    const float* ip = in + (size_t)pix * 64 + t * 32;
    float v[32];
    LDG256(ip, 0);
    LDG256(ip, 8);
    LDG256(ip, 16);
    LDG256(ip, 24);

    // Per quadrant q: out channels 8t+j = v[4j+q], j=0..7 -> one 32B store.
    #pragma unroll
    for (int q = 0; q < 4; q++) {
        const int ro = row + R_ * (q >> 1);
        const int co = col + C_ * (q & 1);
        float* op = out + (((size_t)b * (2 * R_) + ro) * (2 * C_) + co) * 16 + t * 8;
        STG256(op, q);
    }
}

extern "C" void kernel_launch(void* const* d_in, const int* in_sizes, int n_in,
                              void* d_out, int out_size) {
    const float* x = (const float*)d_in[0];
    float* out = (float*)d_out;
    const int threads = 256;
    const int blocks = (NTH + threads - 1) / threads;  // 10000
    upsample_kernel<<<blocks, threads>>>(x, out);
}

// round 4
// speedup vs baseline: 1.0230x; 1.0230x over previous
#include <cuda_runtime.h>

// UpsampleLayer2D: x[B,R,C,64] -> out[B,2R,2C,16]
// out[b, ro, co, c] = x[b, ro%R, co%C, 4c + q],  q = 2*(ro>=R) + (co>=C)
//
// R4: one half-pixel per thread (role pair s in {0,1}).
// Load: 8x LDG.128 covering input channels [32s, 32s+32) = 128B contiguous
//       per thread -> warp reads 4KB fully contiguous.
// Store: per quadrant q, out channels [8s, 8s+8) = 2x STG.128 (32B contiguous
//       per thread) -> warp writes 1KB contiguous per quadrant stream.
// All register-level selection; proven-good 128-bit ops (v8 ops regressed).

#define B_  32
#define R_  200
#define C_  200
#define NPIX (B_ * R_ * C_)        // 1,280,000
#define NTH  (NPIX * 2)            // 2,560,000 threads

__device__ __forceinline__ float comp(const float4& v, int q) {
    switch (q) {
        case 0:  return v.x;
        case 1:  return v.y;
        case 2:  return v.z;
        default: return v.w;
    }
}

__global__ __launch_bounds__(256)
void upsample_kernel(const float* __restrict__ in, float* __restrict__ out) {
    const int idx = blockIdx.x * blockDim.x + threadIdx.x;
    if (idx >= NTH) return;

    const int s   = idx & 1;       // role pair: input channels [32s, 32s+32)
    const int pix = idx >> 1;

    const int col = pix % C_;
    const int tmp = pix / C_;
    const int row = tmp % R_;
    const int b   = tmp / R_;

    // 128B contiguous read: 8 front-batched LDG.128.
    const float4* ip = reinterpret_cast<const float4*>(in) + (size_t)pix * 16 + s * 8;
    float4 v[8];
    #pragma unroll
    for (int j = 0; j < 8; j++) v[j] = __ldcs(ip + j);

    float4* op = reinterpret_cast<float4*>(out);

    // Per quadrant: out channel 8s+m = v[m].comp(q), m=0..7 -> 2x STG.128.
    #pragma unroll
    for (int q = 0; q < 4; q++) {
        const int ro = row + R_ * (q >> 1);
        const int co = col + C_ * (q & 1);
        const size_t obase =
            (((size_t)b * (2 * R_) + ro) * (2 * C_) + co) * 4 + s * 2;
        float4 w0, w1;
        w0.x = comp(v[0], q);  w0.y = comp(v[1], q);
        w0.z = comp(v[2], q);  w0.w = comp(v[3], q);
        w1.x = comp(v[4], q);  w1.y = comp(v[5], q);
        w1.z = comp(v[6], q);  w1.w = comp(v[7], q);
        __stcs(op + obase,     w0);
        __stcs(op + obase + 1, w1);
    }
}

extern "C" void kernel_launch(void* const* d_in, const int* in_sizes, int n_in,
                              void* d_out, int out_size) {
    const float* x = (const float*)d_in[0];
    float* out = (float*)d_out;
    const int threads = 256;
    const int blocks = (NTH + threads - 1) / threads;  // 10000
    upsample_kernel<<<blocks, threads>>>(x, out);
}

// round 5
// speedup vs baseline: 1.1753x; 1.1488x over previous
#include <cuda_runtime.h>

// UpsampleLayer2D: x[B,R,C,64] -> out[B,2R,2C,16]
// out[b, ro, co, c] = x[b, ro%R, co%C, 4c + q],  q = 2*(ro>=R) + (co>=C)
//
// R5: row-aligned blocking. One 800-thread block per (b,row):
//   - 4 threads per pixel (role t), thread loads channels [16t,16t+16) as
//     4x LDG.128 (block reads 51.2KB fully contiguous),
//   - per quadrant one lane-contiguous STG.128 (block writes 4x 12.8KB
//     contiguous, 12.8KB-aligned quadrant streams; no row-boundary splits).

#define B_  32
#define R_  200
#define C_  200
#define NBLK (B_ * R_)   // 6400

__device__ __forceinline__ float comp(const float4& v, int q) {
    switch (q) {
        case 0:  return v.x;
        case 1:  return v.y;
        case 2:  return v.z;
        default: return v.w;
    }
}

__global__ __launch_bounds__(800)
void upsample_kernel(const float* __restrict__ in, float* __restrict__ out) {
    const int b   = blockIdx.x / R_;
    const int row = blockIdx.x % R_;

    const int tid = threadIdx.x;      // 0..799
    const int t   = tid & 3;          // role: input channels [16t, 16t+16)
    const int col = tid >> 2;         // 0..199

    const size_t pix = ((size_t)b * R_ + row) * C_ + col;

    // Contiguous 64B read: channels [16t, 16t+16)
    const float4* ip = reinterpret_cast<const float4*>(in) + pix * 16 + t * 4;
    float4 v0 = ip[0];
    float4 v1 = ip[1];
    float4 v2 = ip[2];
    float4 v3 = ip[3];

    float4* op = reinterpret_cast<float4*>(out);

    #pragma unroll
    for (int q = 0; q < 4; q++) {
        const int ro = row + R_ * (q >> 1);
        const int co = col + C_ * (q & 1);
        const size_t obase =
            (((size_t)b * (2 * R_) + ro) * (2 * C_) + co) * 4 + t;
        float4 w;
        w.x = comp(v0, q);
        w.y = comp(v1, q);
        w.z = comp(v2, q);
        w.w = comp(v3, q);
        op[obase] = w;
    }
}

extern "C" void kernel_launch(void* const* d_in, const int* in_sizes, int n_in,
                              void* d_out, int out_size) {
    const float* x = (const float*)d_in[0];
    float* out = (float*)d_out;
    upsample_kernel<<<NBLK, 800>>>(x, out);
}